// round 4
// baseline (speedup 1.0000x reference)
#include <cuda_runtime.h>
#include <math.h>

#define HID    128
#define NODEF  256
#define NMAX   512
#define NBINS  22
#define ETILE  64
#define TW     256

// ---------------- scratch (device globals; no allocations) ----------------
__device__ float g_n2e[NMAX * HID];
__device__ float g_A[NMAX * HID];          // A[i] = n2e[i]@W1[0:128] + b1 + flow[i]*W1[428]
__device__ float g_B[NMAX * HID];          // B[j] = n2e[j]@W1[128:256] + flow[j]*W1[429]
__device__ float g_R[(2 * NMAX - 1) * HID];// R[d+N-1] = relpos_feats(d)@W1[256:384]

// ---------------- f32x2 helpers ----------------
__device__ __forceinline__ unsigned long long fma2(unsigned long long a, unsigned long long b,
                                                   unsigned long long c) {
    unsigned long long d;
    asm("fma.rn.f32x2 %0, %1, %2, %3;" : "=l"(d) : "l"(a), "l"(b), "l"(c));
    return d;
}
__device__ __forceinline__ unsigned long long dup2(float x) {
    unsigned long long d;
    asm("mov.b64 %0, {%1, %1};" : "=l"(d) : "f"(x));
    return d;
}
__device__ __forceinline__ float2 unpk(unsigned long long a) {
    float2 r;
    asm("mov.b64 {%0, %1}, %2;" : "=f"(r.x), "=f"(r.y) : "l"(a));
    return r;
}

// ---------------- precompute kernels ----------------
__global__ void k_n2e(const float* __restrict__ nf, const float* __restrict__ W,
                      const float* __restrict__ b) {
    __shared__ float row[NODEF];
    const int i = blockIdx.x, c = threadIdx.x;
    row[c]       = nf[i * NODEF + c];
    row[c + 128] = nf[i * NODEF + 128 + c];
    __syncthreads();
    float acc = b[c];
#pragma unroll 8
    for (int k = 0; k < NODEF; k++) acc += row[k] * W[k * HID + c];
    g_n2e[i * HID + c] = acc;
}

__global__ void k_AB(const float* __restrict__ W1, const float* __restrict__ b1,
                     const float* __restrict__ flow) {
    __shared__ float row[HID];
    const int i = blockIdx.x, c = threadIdx.x;
    row[c] = g_n2e[i * HID + c];
    __syncthreads();
    const float fi = flow[i];
    float a  = b1[c] + fi * W1[428 * HID + c];
    float bb = fi * W1[429 * HID + c];
#pragma unroll 8
    for (int k = 0; k < HID; k++) {
        float v = row[k];
        a  += v * W1[k * HID + c];
        bb += v * W1[(128 + k) * HID + c];
    }
    g_A[i * HID + c] = a;
    g_B[i * HID + c] = bb;
}

__global__ void k_R(const float* __restrict__ Wrp, const float* __restrict__ brp,
                    const float* __restrict__ W1, int N) {
    __shared__ float emb[HID];
    __shared__ float rp[HID];
    const int c = threadIdx.x;
    const float d = (float)((int)blockIdx.x - (N - 1));
    if (c < 64) {
        // match fp32 reference semantics: ang = (d * pi_f32) / (2056 ** (k/64)), then sin/cos.
        // Use double transcendental internally (immune to --use_fast_math) on the fp32-rounded angle.
        float den = (float)pow(2056.0, (double)c * (1.0 / 64.0));
        float ang = (d * 3.14159274101257324f) / den;
        emb[c]      = (float)sin((double)ang);
        emb[c + 64] = (float)cos((double)ang);
    }
    __syncthreads();
    float acc = brp[c];
#pragma unroll 8
    for (int k = 0; k < HID; k++) acc += emb[k] * Wrp[k * HID + c];
    rp[c] = acc;
    __syncthreads();
    float r = 0.0f;
#pragma unroll 8
    for (int k = 0; k < HID; k++) r += rp[k] * W1[(256 + k) * HID + c];
    g_R[blockIdx.x * HID + c] = r;
}

// ---------------- distogram bin (matches jnp strict inequalities) ----------------
__device__ __forceinline__ int calc_bin(const float* __restrict__ p, int i, int j) {
    const float dx = __ldg(&p[3 * i + 0]) - __ldg(&p[3 * j + 0]);
    const float dy = __ldg(&p[3 * i + 1]) - __ldg(&p[3 * j + 1]);
    const float dz = __ldg(&p[3 * i + 2]) - __ldg(&p[3 * j + 2]);
    const float d = sqrtf((dx * dx + dy * dy) + dz * dz);
    const float step = (20.0f - 0.001f) / 21.0f;
    int bin = -1;
#pragma unroll
    for (int k = 0; k < NBINS; k++) {
        const float lo = 0.001f + (float)k * step;
        const float hi = (k == NBINS - 1) ? 1e8f : (0.001f + (float)(k + 1) * step);
        if (d > lo && d < hi) bin = k;
    }
    return bin;
}

// ---------------- 64x128x128 fp32 GEMM core (h transposed in smem) ----------------
__device__ __forceinline__ void gemm64(const float* __restrict__ shin,
                                       const float* __restrict__ sW,
                                       int w, int c0, unsigned long long (&acc)[4][4]) {
#pragma unroll
    for (int ep = 0; ep < 4; ep++)
#pragma unroll
        for (int cc = 0; cc < 4; cc++) acc[ep][cc] = 0ULL;
#pragma unroll 4
    for (int k = 0; k < HID; k++) {
        const float* hr = shin + k * 68 + (w << 3);
        const ulonglong2 hA = *reinterpret_cast<const ulonglong2*>(hr);       // edge pairs (0,1)(2,3)
        const ulonglong2 hB = *reinterpret_cast<const ulonglong2*>(hr + 4);   // pairs (4,5)(6,7)
        const float4 wv = *reinterpret_cast<const float4*>(sW + k * HID + c0);
        unsigned long long hp[4] = {hA.x, hA.y, hB.x, hB.y};
        unsigned long long wd[4] = {dup2(wv.x), dup2(wv.y), dup2(wv.z), dup2(wv.w)};
#pragma unroll
        for (int ep = 0; ep < 4; ep++)
#pragma unroll
            for (int cc = 0; cc < 4; cc++)
                acc[ep][cc] = fma2(hp[ep], wd[cc], acc[ep][cc]);
    }
}

// ---------------- main persistent kernel ----------------
// smem layout (floats): W2 16384 | W3 16384 | Wtail 5632 | h1 8704 | h2 8704 |
//                       A 128 | b2 128 | b3 128 | g 128 | beta 128 | bins 128
#define SMEM_FLOATS 56576
#define SMEM_BYTES  (SMEM_FLOATS * 4)

__global__ void __launch_bounds__(TW, 1) k_main(
    const float* __restrict__ trans, const float* __restrict__ sctrans,
    const float* __restrict__ emask, const float* __restrict__ W1,
    const float* __restrict__ W2, const float* __restrict__ b2,
    const float* __restrict__ W3, const float* __restrict__ b3,
    const float* __restrict__ lng, const float* __restrict__ lnb,
    float* __restrict__ out, int N) {
    extern __shared__ float sm[];
    float* sW2 = sm;
    float* sW3 = sm + 16384;
    float* sWT = sm + 32768;   // 44*128: dist rows then sc rows
    float* sh1 = sm + 38400;   // [128][68] transposed
    float* sh2 = sm + 47104;   // [128][68]
    float* sA  = sm + 55808;
    float* sb2 = sm + 55936;
    float* sb3 = sm + 56064;
    float* sg  = sm + 56192;
    float* sbt = sm + 56320;
    int* sbin1 = (int*)(sm + 56448);
    int* sbin2 = sbin1 + ETILE;

    const int tid = threadIdx.x;
    for (int idx = tid; idx < HID * HID; idx += TW) {
        sW2[idx] = W2[idx];
        sW3[idx] = W3[idx];
    }
    for (int idx = tid; idx < 44 * HID; idx += TW) sWT[idx] = W1[384 * HID + idx];
    if (tid < HID) {
        sb2[tid] = b2[tid];
        sb3[tid] = b3[tid];
        sg[tid]  = lng[tid];
        sbt[tid] = lnb[tid];
    }
    __syncthreads();

    const int lane = tid & 31;
    const int w = tid >> 5;       // warp = 8 edges
    const int c0 = lane << 2;     // lane = 4 channels
    const int tilesPerRow = N / ETILE;
    const int ntiles = N * tilesPerRow;

    for (int t = blockIdx.x; t < ntiles; t += gridDim.x) {
        const int i = t / tilesPerRow;
        const int jb = (t - i * tilesPerRow) * ETILE;

        if (tid < ETILE) {
            const int j = jb + tid;
            sbin1[tid] = calc_bin(trans, i, j);
            sbin2[tid] = calc_bin(sctrans, i, j);
        } else if (tid < ETILE + HID) {
            const int c = tid - ETILE;
            sA[c] = g_A[i * HID + c];
        }
        __syncthreads();

        // ---- h1 assembly (table adds + relu), transposed store ----
        {
            const int c = tid & 127;
            const float a = sA[c];
            for (int e = (tid >> 7); e < ETILE; e += 2) {
                const int j = jb + e;
                float v = a + __ldg(&g_B[j * HID + c]) +
                          __ldg(&g_R[(i - j + (N - 1)) * HID + c]);
                const int q1 = sbin1[e];
                if (q1 >= 0) v += sWT[q1 * HID + c];
                const int q2 = sbin2[e];
                if (q2 >= 0) v += sWT[(NBINS + q2) * HID + c];
                sh1[c * 68 + e] = fmaxf(v, 0.0f);
            }
        }
        __syncthreads();

        // ---- layer 2: h2 = relu(h1 @ W2 + b2) ----
        {
            unsigned long long acc[4][4];
            gemm64(sh1, sW2, w, c0, acc);
#pragma unroll
            for (int cc = 0; cc < 4; cc++) {
                const float b = sb2[c0 + cc];
                float2 p0 = unpk(acc[0][cc]);
                float2 p1 = unpk(acc[1][cc]);
                float2 p2 = unpk(acc[2][cc]);
                float2 p3 = unpk(acc[3][cc]);
                float4 q0 = make_float4(fmaxf(p0.x + b, 0.f), fmaxf(p0.y + b, 0.f),
                                        fmaxf(p1.x + b, 0.f), fmaxf(p1.y + b, 0.f));
                float4 q1 = make_float4(fmaxf(p2.x + b, 0.f), fmaxf(p2.y + b, 0.f),
                                        fmaxf(p3.x + b, 0.f), fmaxf(p3.y + b, 0.f));
                float* d = &sh2[(c0 + cc) * 68 + (w << 3)];
                *reinterpret_cast<float4*>(d) = q0;
                *reinterpret_cast<float4*>(d + 4) = q1;
            }
        }
        __syncthreads();

        // ---- layer 3 + LayerNorm + mask + store ----
        {
            unsigned long long acc[4][4];
            gemm64(sh2, sW3, w, c0, acc);
            float v[8][4];
#pragma unroll
            for (int cc = 0; cc < 4; cc++) {
                const float b = sb3[c0 + cc];
#pragma unroll
                for (int ep = 0; ep < 4; ep++) {
                    float2 p = unpk(acc[ep][cc]);
                    v[2 * ep][cc]     = p.x + b;
                    v[2 * ep + 1][cc] = p.y + b;
                }
            }
            const float g0 = sg[c0], g1 = sg[c0 + 1], g2 = sg[c0 + 2], g3 = sg[c0 + 3];
            const float t0 = sbt[c0], t1 = sbt[c0 + 1], t2 = sbt[c0 + 2], t3 = sbt[c0 + 3];
#pragma unroll
            for (int e = 0; e < 8; e++) {
                float s = (v[e][0] + v[e][1]) + (v[e][2] + v[e][3]);
#pragma unroll
                for (int off = 16; off > 0; off >>= 1)
                    s += __shfl_xor_sync(0xffffffffu, s, off);
                const float mu = s * (1.0f / 128.0f);
                const float d0 = v[e][0] - mu, d1 = v[e][1] - mu;
                const float d2 = v[e][2] - mu, d3 = v[e][3] - mu;
                float q = (d0 * d0 + d1 * d1) + (d2 * d2 + d3 * d3);
#pragma unroll
                for (int off = 16; off > 0; off >>= 1)
                    q += __shfl_xor_sync(0xffffffffu, q, off);
                const float rstd = 1.0f / sqrtf(q * (1.0f / 128.0f) + 1e-5f);
                const int j = jb + (w << 3) + e;
                const float m = __ldg(&emask[i * N + j]);
                float4 o;
                o.x = (d0 * rstd * g0 + t0) * m;
                o.y = (d1 * rstd * g1 + t1) * m;
                o.z = (d2 * rstd * g2 + t2) * m;
                o.w = (d3 * rstd * g3 + t3) * m;
                *reinterpret_cast<float4*>(&out[((size_t)(i * N + j)) * HID + c0]) = o;
            }
        }
    }
}

// ---------------- launch ----------------
extern "C" void kernel_launch(void* const* d_in, const int* in_sizes, int n_in,
                              void* d_out, int out_size) {
    const float* nf     = (const float*)d_in[0];
    const float* trans  = (const float*)d_in[1];
    const float* sct    = (const float*)d_in[2];
    const float* emask  = (const float*)d_in[3];
    const float* flow   = (const float*)d_in[4];
    const float* W_n2e  = (const float*)d_in[5];
    const float* b_n2e  = (const float*)d_in[6];
    const float* W_rp   = (const float*)d_in[7];
    const float* b_rp   = (const float*)d_in[8];
    const float* W1     = (const float*)d_in[9];
    const float* b1     = (const float*)d_in[10];
    const float* W2     = (const float*)d_in[11];
    const float* b2     = (const float*)d_in[12];
    const float* W3     = (const float*)d_in[13];
    const float* b3     = (const float*)d_in[14];
    const float* lng    = (const float*)d_in[15];
    const float* lnb    = (const float*)d_in[16];
    float* out = (float*)d_out;

    const int N = in_sizes[4];  // flow_mask length

    k_n2e<<<N, 128>>>(nf, W_n2e, b_n2e);
    k_AB<<<N, 128>>>(W1, b1, flow);
    k_R<<<2 * N - 1, 128>>>(W_rp, b_rp, W1, N);

    cudaFuncSetAttribute((const void*)k_main,
                         cudaFuncAttributeMaxDynamicSharedMemorySize, SMEM_BYTES);
    k_main<<<152, TW, SMEM_BYTES>>>(trans, sct, emask, W1, W2, b2, W3, b3,
                                    lng, lnb, out, N);
}

// round 5
// speedup vs baseline: 1.0269x; 1.0269x over previous
#include <cuda_runtime.h>
#include <math.h>

#define HID    128
#define NODEF  256
#define NMAX   512
#define NBINS  22
#define ETILE  64
#define TW     512

// ---------------- scratch (device globals; no allocations) ----------------
__device__ float g_n2e[NMAX * HID];
__device__ float g_A[NMAX * HID];          // A[i] = n2e[i]@W1[0:128] + b1 + flow[i]*W1[428]
__device__ float g_B[NMAX * HID];          // B[j] = n2e[j]@W1[128:256] + flow[j]*W1[429]
__device__ float g_R[(2 * NMAX - 1) * HID];// R[d+N-1] = relpos_feats(d)@W1[256:384]

// ---------------- f32x2 helpers ----------------
__device__ __forceinline__ unsigned long long fma2(unsigned long long a, unsigned long long b,
                                                   unsigned long long c) {
    unsigned long long d;
    asm("fma.rn.f32x2 %0, %1, %2, %3;" : "=l"(d) : "l"(a), "l"(b), "l"(c));
    return d;
}
__device__ __forceinline__ unsigned long long dup2(float x) {
    unsigned long long d;
    asm("mov.b64 %0, {%1, %1};" : "=l"(d) : "f"(x));
    return d;
}
__device__ __forceinline__ float2 unpk(unsigned long long a) {
    float2 r;
    asm("mov.b64 {%0, %1}, %2;" : "=f"(r.x), "=f"(r.y) : "l"(a));
    return r;
}

// ---------------- precompute kernels ----------------
__global__ void k_n2e(const float* __restrict__ nf, const float* __restrict__ W,
                      const float* __restrict__ b) {
    __shared__ float row[NODEF];
    const int i = blockIdx.x, c = threadIdx.x;
    row[c]       = nf[i * NODEF + c];
    row[c + 128] = nf[i * NODEF + 128 + c];
    __syncthreads();
    float acc = b[c];
#pragma unroll 8
    for (int k = 0; k < NODEF; k++) acc += row[k] * W[k * HID + c];
    g_n2e[i * HID + c] = acc;
}

__global__ void k_AB(const float* __restrict__ W1, const float* __restrict__ b1,
                     const float* __restrict__ flow) {
    __shared__ float row[HID];
    const int i = blockIdx.x, c = threadIdx.x;
    row[c] = g_n2e[i * HID + c];
    __syncthreads();
    const float fi = flow[i];
    float a  = b1[c] + fi * W1[428 * HID + c];
    float bb = fi * W1[429 * HID + c];
#pragma unroll 8
    for (int k = 0; k < HID; k++) {
        float v = row[k];
        a  += v * W1[k * HID + c];
        bb += v * W1[(128 + k) * HID + c];
    }
    g_A[i * HID + c] = a;
    g_B[i * HID + c] = bb;
}

__global__ void k_R(const float* __restrict__ Wrp, const float* __restrict__ brp,
                    const float* __restrict__ W1, int N) {
    __shared__ float emb[HID];
    __shared__ float rp[HID];
    const int c = threadIdx.x;
    const float d = (float)((int)blockIdx.x - (N - 1));
    if (c < 64) {
        // match fp32 reference semantics: ang = (d * pi_f32) / (2056 ** (k/64)), then sin/cos.
        // Double transcendental internally (immune to --use_fast_math) on the fp32-rounded angle.
        float den = (float)pow(2056.0, (double)c * (1.0 / 64.0));
        float ang = (d * 3.14159274101257324f) / den;
        emb[c]      = (float)sin((double)ang);
        emb[c + 64] = (float)cos((double)ang);
    }
    __syncthreads();
    float acc = brp[c];
#pragma unroll 8
    for (int k = 0; k < HID; k++) acc += emb[k] * Wrp[k * HID + c];
    rp[c] = acc;
    __syncthreads();
    float r = 0.0f;
#pragma unroll 8
    for (int k = 0; k < HID; k++) r += rp[k] * W1[(256 + k) * HID + c];
    g_R[blockIdx.x * HID + c] = r;
}

// ---------------- distogram bin (matches jnp strict inequalities) ----------------
__device__ __forceinline__ int calc_bin(const float* __restrict__ p, int i, int j) {
    const float dx = __ldg(&p[3 * i + 0]) - __ldg(&p[3 * j + 0]);
    const float dy = __ldg(&p[3 * i + 1]) - __ldg(&p[3 * j + 1]);
    const float dz = __ldg(&p[3 * i + 2]) - __ldg(&p[3 * j + 2]);
    const float d = sqrtf((dx * dx + dy * dy) + dz * dz);
    const float step = (20.0f - 0.001f) / 21.0f;
    int bin = -1;
#pragma unroll
    for (int k = 0; k < NBINS; k++) {
        const float lo = 0.001f + (float)k * step;
        const float hi = (k == NBINS - 1) ? 1e8f : (0.001f + (float)(k + 1) * step);
        if (d > lo && d < hi) bin = k;
    }
    return bin;
}

// ---------------- 64x128x128 fp32 GEMM core (h transposed in smem) ----------------
// 16 warps; warp w owns 4 edges [4w, 4w+4); each lane owns 4 channels c0=lane*4.
// Per-thread accumulator tile: 4 edges (2 f32x2 pairs) x 4 channels.
__device__ __forceinline__ void gemm64(const float* __restrict__ shin,
                                       const float* __restrict__ sW,
                                       int w, int c0, unsigned long long (&acc)[2][4]) {
#pragma unroll
    for (int ep = 0; ep < 2; ep++)
#pragma unroll
        for (int cc = 0; cc < 4; cc++) acc[ep][cc] = 0ULL;
#pragma unroll 4
    for (int k = 0; k < HID; k++) {
        const ulonglong2 hA = *reinterpret_cast<const ulonglong2*>(shin + k * 68 + (w << 2));
        const float4 wv = *reinterpret_cast<const float4*>(sW + k * HID + c0);
        unsigned long long hp[2] = {hA.x, hA.y};
        unsigned long long wd[4] = {dup2(wv.x), dup2(wv.y), dup2(wv.z), dup2(wv.w)};
#pragma unroll
        for (int ep = 0; ep < 2; ep++)
#pragma unroll
            for (int cc = 0; cc < 4; cc++)
                acc[ep][cc] = fma2(hp[ep], wd[cc], acc[ep][cc]);
    }
}

// ---------------- main persistent kernel ----------------
// smem layout (floats): W2 16384 | W3 16384 | Wtail 5632 | h1 8704 | h2 8704 |
//                       A 128 | b2 128 | b3 128 | g 128 | beta 128 | bins 128
#define SMEM_FLOATS 56576
#define SMEM_BYTES  (SMEM_FLOATS * 4)

__global__ void __launch_bounds__(TW, 1) k_main(
    const float* __restrict__ trans, const float* __restrict__ sctrans,
    const float* __restrict__ emask, const float* __restrict__ W1,
    const float* __restrict__ W2, const float* __restrict__ b2,
    const float* __restrict__ W3, const float* __restrict__ b3,
    const float* __restrict__ lng, const float* __restrict__ lnb,
    float* __restrict__ out, int N) {
    extern __shared__ float sm[];
    float* sW2 = sm;
    float* sW3 = sm + 16384;
    float* sWT = sm + 32768;   // 44*128: dist rows then sc rows
    float* sh1 = sm + 38400;   // [128][68] transposed
    float* sh2 = sm + 47104;   // [128][68]
    float* sA  = sm + 55808;
    float* sb2 = sm + 55936;
    float* sb3 = sm + 56064;
    float* sg  = sm + 56192;
    float* sbt = sm + 56320;
    int* sbin1 = (int*)(sm + 56448);
    int* sbin2 = sbin1 + ETILE;

    const int tid = threadIdx.x;
    for (int idx = tid; idx < HID * HID; idx += TW) {
        sW2[idx] = W2[idx];
        sW3[idx] = W3[idx];
    }
    for (int idx = tid; idx < 44 * HID; idx += TW) sWT[idx] = W1[384 * HID + idx];
    if (tid < HID) {
        sb2[tid] = b2[tid];
        sb3[tid] = b3[tid];
        sg[tid]  = lng[tid];
        sbt[tid] = lnb[tid];
    }
    __syncthreads();

    const int lane = tid & 31;
    const int w = tid >> 5;       // 16 warps; warp = 4 edges
    const int c0 = lane << 2;     // lane = 4 channels
    const int tilesPerRow = N / ETILE;
    const int ntiles = N * tilesPerRow;

    for (int t = blockIdx.x; t < ntiles; t += gridDim.x) {
        const int i = t / tilesPerRow;
        const int jb = (t - i * tilesPerRow) * ETILE;

        if (tid < ETILE) {
            const int j = jb + tid;
            sbin1[tid] = calc_bin(trans, i, j);
            sbin2[tid] = calc_bin(sctrans, i, j);
        } else if (tid < ETILE + HID) {
            const int c = tid - ETILE;
            sA[c] = g_A[i * HID + c];
        }
        __syncthreads();

        // ---- h1 assembly (table adds + relu), transposed store ----
        {
            const int c = tid & 127;
            const float a = sA[c];
            for (int e = (tid >> 7); e < ETILE; e += 4) {
                const int j = jb + e;
                float v = a + __ldg(&g_B[j * HID + c]) +
                          __ldg(&g_R[(i - j + (N - 1)) * HID + c]);
                const int q1 = sbin1[e];
                if (q1 >= 0) v += sWT[q1 * HID + c];
                const int q2 = sbin2[e];
                if (q2 >= 0) v += sWT[(NBINS + q2) * HID + c];
                sh1[c * 68 + e] = fmaxf(v, 0.0f);
            }
        }
        __syncthreads();

        // ---- layer 2: h2 = relu(h1 @ W2 + b2) ----
        {
            unsigned long long acc[2][4];
            gemm64(sh1, sW2, w, c0, acc);
#pragma unroll
            for (int cc = 0; cc < 4; cc++) {
                const float b = sb2[c0 + cc];
                float2 p0 = unpk(acc[0][cc]);
                float2 p1 = unpk(acc[1][cc]);
                float4 q = make_float4(fmaxf(p0.x + b, 0.f), fmaxf(p0.y + b, 0.f),
                                       fmaxf(p1.x + b, 0.f), fmaxf(p1.y + b, 0.f));
                *reinterpret_cast<float4*>(&sh2[(c0 + cc) * 68 + (w << 2)]) = q;
            }
        }
        __syncthreads();

        // ---- layer 3 + LayerNorm + mask + store ----
        {
            unsigned long long acc[2][4];
            gemm64(sh2, sW3, w, c0, acc);
            float v[4][4];
#pragma unroll
            for (int cc = 0; cc < 4; cc++) {
                const float b = sb3[c0 + cc];
#pragma unroll
                for (int ep = 0; ep < 2; ep++) {
                    float2 p = unpk(acc[ep][cc]);
                    v[2 * ep][cc]     = p.x + b;
                    v[2 * ep + 1][cc] = p.y + b;
                }
            }
            const float g0 = sg[c0], g1 = sg[c0 + 1], g2 = sg[c0 + 2], g3 = sg[c0 + 3];
            const float t0 = sbt[c0], t1 = sbt[c0 + 1], t2 = sbt[c0 + 2], t3 = sbt[c0 + 3];
#pragma unroll
            for (int e = 0; e < 4; e++) {
                float s = (v[e][0] + v[e][1]) + (v[e][2] + v[e][3]);
#pragma unroll
                for (int off = 16; off > 0; off >>= 1)
                    s += __shfl_xor_sync(0xffffffffu, s, off);
                const float mu = s * (1.0f / 128.0f);
                const float d0 = v[e][0] - mu, d1 = v[e][1] - mu;
                const float d2 = v[e][2] - mu, d3 = v[e][3] - mu;
                float q = (d0 * d0 + d1 * d1) + (d2 * d2 + d3 * d3);
#pragma unroll
                for (int off = 16; off > 0; off >>= 1)
                    q += __shfl_xor_sync(0xffffffffu, q, off);
                const float rstd = 1.0f / sqrtf(q * (1.0f / 128.0f) + 1e-5f);
                const int j = jb + (w << 2) + e;
                const float m = __ldg(&emask[i * N + j]);
                float4 o;
                o.x = (d0 * rstd * g0 + t0) * m;
                o.y = (d1 * rstd * g1 + t1) * m;
                o.z = (d2 * rstd * g2 + t2) * m;
                o.w = (d3 * rstd * g3 + t3) * m;
                *reinterpret_cast<float4*>(&out[((size_t)(i * N + j)) * HID + c0]) = o;
            }
        }
    }
}

// ---------------- launch ----------------
extern "C" void kernel_launch(void* const* d_in, const int* in_sizes, int n_in,
                              void* d_out, int out_size) {
    const float* nf     = (const float*)d_in[0];
    const float* trans  = (const float*)d_in[1];
    const float* sct    = (const float*)d_in[2];
    const float* emask  = (const float*)d_in[3];
    const float* flow   = (const float*)d_in[4];
    const float* W_n2e  = (const float*)d_in[5];
    const float* b_n2e  = (const float*)d_in[6];
    const float* W_rp   = (const float*)d_in[7];
    const float* b_rp   = (const float*)d_in[8];
    const float* W1     = (const float*)d_in[9];
    const float* b1     = (const float*)d_in[10];
    const float* W2     = (const float*)d_in[11];
    const float* b2     = (const float*)d_in[12];
    const float* W3     = (const float*)d_in[13];
    const float* b3     = (const float*)d_in[14];
    const float* lng    = (const float*)d_in[15];
    const float* lnb    = (const float*)d_in[16];
    float* out = (float*)d_out;

    const int N = in_sizes[4];  // flow_mask length

    k_n2e<<<N, 128>>>(nf, W_n2e, b_n2e);
    k_AB<<<N, 128>>>(W1, b1, flow);
    k_R<<<2 * N - 1, 128>>>(W_rp, b_rp, W1, N);

    cudaFuncSetAttribute((const void*)k_main,
                         cudaFuncAttributeMaxDynamicSharedMemorySize, SMEM_BYTES);
    k_main<<<152, TW, SMEM_BYTES>>>(trans, sct, emask, W1, W2, b2, W3, b3,
                                    lng, lnb, out, N);
}